// round 9
// baseline (speedup 1.0000x reference)
#include <cuda_runtime.h>
#include <math.h>

#define BATCH 64
#define NPTS  512
#define DIM   512
#define NIDS  32                       // track ids are in [-1, 32)
#define DTHREADS 128
#define DWARPS (DTHREADS / 32)         // 4
#define IDBLOCKS (BATCH * NIDS)        // 2048: one block per (batch, id)
#define ROWS_PER_THREAD (NPTS / DTHREADS)  // 4

__device__ __constant__ float c_margin = 0.3f;
__device__ __constant__ float c_eps    = 1e-6f;

// scratch (no allocations allowed) — zero-initialized; last block resets.
__device__ float        g_tot;
__device__ int          g_cntall;
__device__ unsigned int g_ticket;

// accumulate |a4-q4+eps|^2 into acc
#define ACC4(a4, q4, acc)                              \
    do {                                               \
        float d_;                                      \
        d_ = (a4).x - (q4).x + eps; acc = fmaf(d_, d_, acc); \
        d_ = (a4).y - (q4).y + eps; acc = fmaf(d_, d_, acc); \
        d_ = (a4).z - (q4).z + eps; acc = fmaf(d_, d_, acc); \
        d_ = (a4).w - (q4).w + eps; acc = fmaf(d_, d_, acc); \
    } while (0)

// ---------------------------------------------------------------------------
// R9: schedule by (batch, id) instead of (batch, index-range).
// All anchors of one id share ONE positive row (first, or second for the
// anchor that IS first) and ONE negative row (j1 or j2, fixed per block).
// Those two rows are preloaded into registers; per anchor the warp issues
// only the 4 LDG.128 of the anchor row. L2 traffic drops ~130MB -> ~77MB and
// per-anchor latency exposure drops 12 loads -> 4.
//
// Closed-form replacement for argmax-of-mask (ids in [-1, 32)):
//   pos(i) = first[m] != i ? first[m] : second[m]     (needs count[m] >= 2)
//   neg(i) = ids[j1] != m ? j1 : j2                   (needs nvalid > count[m])
// ---------------------------------------------------------------------------
__global__ void __launch_bounds__(DTHREADS)
dist_kernel(const float* __restrict__ feats,
            const int*   __restrict__ ids,
            float*       __restrict__ out,
            int out_size)
{
    const int blk  = blockIdx.x;
    const int b    = blk >> 5;           // batch
    const int myid = blk & 31;           // track id this block owns
    const int t    = threadIdx.x;
    const int wid  = t >> 5;
    const int lane = t & 31;

    __shared__ int s_first, s_second, s_j1, s_j2, s_idj1;
    __shared__ int s_n, s_nv, s_cm;
    __shared__ float s_tot;
    __shared__ int   s_cnt;
    __shared__ int s_list[NPTS];

    if (t == 0) {
        s_first = 0x7fffffff; s_second = 0x7fffffff;
        s_j1 = 0x7fffffff;    s_j2 = 0x7fffffff;
        s_n = 0; s_nv = 0; s_cm = 0;
        s_tot = 0.0f; s_cnt = 0;
    }
    __syncthreads();

    const int* __restrict__ bid = ids + b * NPTS;

    // Pass 1: first occurrence of myid, first valid overall, counts.
    int idr[ROWS_PER_THREAD];
    int lv = 0, lm = 0;
    #pragma unroll
    for (int r = 0; r < ROWS_PER_THREAD; ++r) {
        const int i = t + DTHREADS * r;
        idr[r] = bid[i];
        if (idr[r] >= 0) {
            lv++;
            atomicMin(&s_j1, i);
            if (idr[r] == myid) { lm++; atomicMin(&s_first, i); }
        }
    }
    #pragma unroll
    for (int o = 16; o > 0; o >>= 1) {
        lv += __shfl_xor_sync(0xFFFFFFFFu, lv, o);
        lm += __shfl_xor_sync(0xFFFFFFFFu, lm, o);
    }
    if (lane == 0) { atomicAdd(&s_nv, lv); atomicAdd(&s_cm, lm); }
    __syncthreads();
    if (t == 0) s_idj1 = (s_j1 < NPTS) ? bid[s_j1] : -2;
    __syncthreads();

    // Pass 2: second occurrence of myid; first valid with id != ids[j1];
    // compact this id's anchor list.
    const int first = s_first;
    const int idj1  = s_idj1;
    #pragma unroll
    for (int r = 0; r < ROWS_PER_THREAD; ++r) {
        const int i = t + DTHREADS * r;
        if (idr[r] == myid) {
            if (i != first) atomicMin(&s_second, i);
            const int k = atomicAdd(&s_n, 1);
            s_list[k] = i;
        }
        if (idr[r] >= 0 && idr[r] != idj1) atomicMin(&s_j2, i);
    }
    __syncthreads();

    const int cm = s_cm;
    const int nv = s_nv;

    float w_tot = 0.0f;
    int   w_cnt = 0;

    if (cm >= 2 && nv > cm) {           // anchors of this id are all ok
        const int second = s_second;
        const int nidx   = (idj1 != myid) ? s_j1 : s_j2;
        const float* __restrict__ base = feats + (size_t)b * NPTS * DIM;
        const float eps = c_eps;

        // Preload the shared positive row (first) and negative row into regs.
        const float4* __restrict__ fP = (const float4*)(base + (size_t)first * DIM);
        const float4* __restrict__ fN = (const float4*)(base + (size_t)nidx  * DIM);
        const float4 P0 = fP[lane], P1 = fP[lane + 32], P2 = fP[lane + 64], P3 = fP[lane + 96];
        const float4 N0 = fN[lane], N1 = fN[lane + 32], N2 = fN[lane + 64], N3 = fN[lane + 96];

        for (int idx = wid; idx < cm; idx += DWARPS) {
            const int i = s_list[idx];
            const float4* __restrict__ fA = (const float4*)(base + (size_t)i * DIM);
            const float4 A0 = __ldcs(fA + lane);
            const float4 A1 = __ldcs(fA + lane + 32);
            const float4 A2 = __ldcs(fA + lane + 64);
            const float4 A3 = __ldcs(fA + lane + 96);

            float sap = 0.0f, san = 0.0f;
            ACC4(A0, N0, san); ACC4(A1, N1, san);
            ACC4(A2, N2, san); ACC4(A3, N3, san);

            if (i != first) {
                ACC4(A0, P0, sap); ACC4(A1, P1, sap);
                ACC4(A2, P2, sap); ACC4(A3, P3, sap);
            } else {
                // the anchor that IS `first` pairs with `second`
                const float4* __restrict__ fS =
                    (const float4*)(base + (size_t)second * DIM);
                const float4 S0 = fS[lane], S1 = fS[lane + 32],
                             S2 = fS[lane + 64], S3 = fS[lane + 96];
                ACC4(A0, S0, sap); ACC4(A1, S1, sap);
                ACC4(A2, S2, sap); ACC4(A3, S3, sap);
            }

            #pragma unroll
            for (int o = 16; o > 0; o >>= 1) {
                sap += __shfl_xor_sync(0xFFFFFFFFu, sap, o);
                san += __shfl_xor_sync(0xFFFFFFFFu, san, o);
            }
            if (lane == 0) {
                const float per = sqrtf(sap) - sqrtf(san) + c_margin;
                if (per > 0.0f) w_tot += per;
                w_cnt++;
            }
        }
    }

    if (lane == 0) {
        atomicAdd(&s_tot, w_tot);
        atomicAdd(&s_cnt, w_cnt);
    }
    __syncthreads();

    if (t == 0) {
        atomicAdd(&g_tot, s_tot);
        atomicAdd(&g_cntall, s_cnt);
        __threadfence();
        const unsigned int old = atomicAdd(&g_ticket, 1u);
        if (old == IDBLOCKS - 1) {
            __threadfence();                 // see all blocks' adds
            const float T = g_tot;
            const int   C = g_cntall;
            const float loss = (C > 0) ? (T / (float)C) : 0.0f;
            if (out_size > 0) out[0] = loss; // tracking_loss
            if (out_size > 1) out[1] = loss; // loss_triplet
            if (out_size > 2) out[2] = 0.0f; // loss_id
            g_tot    = 0.0f;                 // reset for next graph replay
            g_cntall = 0;
            g_ticket = 0;
            __threadfence();
        }
    }
}

extern "C" void kernel_launch(void* const* d_in, const int* in_sizes, int n_in,
                              void* d_out, int out_size)
{
    const float* feats = (const float*)d_in[0];
    const int*   ids   = (const int*)d_in[1];
    float*       out   = (float*)d_out;

    dist_kernel<<<IDBLOCKS, DTHREADS>>>(feats, ids, out, out_size);
}